// round 12
// baseline (speedup 1.0000x reference)
#include <cuda_runtime.h>
#include <cstdint>

namespace {

constexpr int KNUM  = 32;           // pole pairs total (64 poles as 32 conj pairs)
constexpr int KP    = 4;            // packed pairs-of-poles per THREAD (8 poles)
constexpr int DDIM  = 1024;
constexpr int LLEN  = 2048;
constexpr int CHUNK = 64;           // output elements per thread
constexpr int NCH   = LLEN / CHUNK; // 32 chunks per row

using u64 = unsigned long long;

// ---- packed f32x2 primitives (sm_103a dual-lane fp32 path) ----
__device__ __forceinline__ u64 pk2(float lo, float hi) {
    u64 r; asm("mov.b64 %0, {%1, %2};" : "=l"(r) : "f"(lo), "f"(hi)); return r;
}
__device__ __forceinline__ void unpk2(u64 v, float& lo, float& hi) {
    asm("mov.b64 {%0, %1}, %2;" : "=f"(lo), "=f"(hi) : "l"(v));
}
__device__ __forceinline__ u64 add2(u64 a, u64 b) {
    u64 d; asm("add.rn.f32x2 %0, %1, %2;" : "=l"(d) : "l"(a), "l"(b)); return d;
}
__device__ __forceinline__ u64 mul2(u64 a, u64 b) {
    u64 d; asm("mul.rn.f32x2 %0, %1, %2;" : "=l"(d) : "l"(a), "l"(b)); return d;
}
__device__ __forceinline__ u64 fma2(u64 a, u64 b, u64 c) {
    u64 d; asm("fma.rn.f32x2 %0, %1, %2, %3;" : "=l"(d) : "l"(a), "l"(b), "l"(c)); return d;
}
__device__ __forceinline__ float fast_lg2(float x) {
    float y; asm("lg2.approx.f32 %0, %1;" : "=f"(y) : "f"(x)); return y;
}
__device__ __forceinline__ float fast_ex2(float x) {
    float y; asm("ex2.approx.f32 %0, %1;" : "=f"(y) : "f"(x)); return y;
}

// Split-K=4 decomposition. Warp = (d, 8 chunks x 4 pole-quarters):
//   lane = q*8 + c3   (q = lane>>3: pole quarter, c3 = lane&7: chunk-in-warp)
//   c = (warp&3)*8 + c3  (32 chunks of 64 taps per row), d = warp>>2.
// Each thread runs 4 packed pairs (8 poles) for its chunk; two shfl_xor stages
// (8 then 16) merge the 4 quarter-partials; lanes q==0 store.
// Recurrence per pole: x(t+1) = a*x(t) + b*x(t-1), a = 2 r cos(theta), b = -r^2,
// packed 2 poles per f32x2. Chunk starts re-anchored from closed form (all-float,
// exact twoprod + Cody-Waite phase reduction) so error never accumulates >64 steps.
//
// 2048 blocks of 64 @ 14 blocks/SM resident (<=73 regs) = one full wave,
// 28 warps/SM (7/SMSP): latency+tail were the R10 binding constraints.
__global__ void __launch_bounds__(64, 14)
modal_filter_kernel(const float* __restrict__ rr_,
                    const float* __restrict__ th_,
                    const float* __restrict__ Rre_,
                    const float* __restrict__ Rim_,
                    const float* __restrict__ h0_,
                    float* __restrict__ out)
{
    const int gtid = blockIdx.x * 64 + threadIdx.x;
    const int warp = gtid >> 5;
    const int lane = gtid & 31;
    const int d    = warp >> 2;                        // channel row (warp-uniform)
    const int c    = ((warp & 3) << 3) + (lane & 7);   // chunk 0..31
    const int q    = lane >> 3;                        // pole quarter 0..3

    // Output window [64c, 64c+64). Output j maps to series index t = j-1
    // (j = 0 is h_0), so this chunk's series starts at t0 = 64c - 1.
    const float t0f = (float)(CHUNK * c - 1);

    u64 A[KP], B[KP], X[KP], XM[KP];

    #pragma unroll
    for (int kp = 0; kp < KP; kp++) {
        float av[2], bv[2], x0[2], x1[2];
        #pragma unroll
        for (int j = 0; j < 2; j++) {
            const int k = q * 8 + kp * 2 + j;
            const float rv = __ldg(&rr_ [k * DDIM + d]);
            const float tv = __ldg(&th_ [k * DDIM + d]);
            const float Rr = __ldg(&Rre_[k * DDIM + d]);
            const float Ri = __ldg(&Rim_[k * DDIM + d]);

            float sT, cT;
            __sincosf(tv, &sT, &cT);             // arg in [0, 2pi): fast path fine
            const float pre = rv * cT;
            const float pim = rv * sT;
            av[j] = pre + pre;                   // 2 r cos(theta)
            bv[j] = -(rv * rv);                  // -r^2

            // amp = r^t0 via MUFU lg2/ex2. Exponent abs err <= |t0|*2^-22:
            // only meaningful where amp ~1 (small t0) -> <1e-5 output impact.
            const float amp = fast_ex2(t0f * fast_lg2(rv));

            // phase = t0*theta mod 2pi, all-float: exact twoprod, then 2-constant
            // Cody-Waite. Residual ~1e-6 rad.
            const float hi = t0f * tv;
            const float lo = __fmaf_rn(t0f, tv, -hi);     // exact residual
            const float nn = rintf(hi * 0.15915494309f);  // 1/(2pi)
            float red = __fmaf_rn(nn, -6.28125f, hi);     // 2pi hi (13-bit exact)
            red = __fmaf_rn(nn, -1.9353071795864769e-3f, red); // 2pi - 6.28125
            red += lo;
            float sA, cA;
            __sincosf(red, &sA, &cA);

            const float wre = amp * (Rr * cA - Ri * sA);   // Re(R p^t0)
            const float wim = amp * (Rr * sA + Ri * cA);   // Im(R p^t0)
            x0[j] = wre;                                   // x(t0)
            x1[j] = wre * pre - wim * pim;                 // x(t0+1)
        }
        A[kp]  = pk2(av[0], av[1]);
        B[kp]  = pk2(bv[0], bv[1]);
        XM[kp] = pk2(x0[0], x0[1]);
        X[kp]  = pk2(x1[0], x1[1]);
    }

    float* op = out + (size_t)d * LLEN + c * CHUNK;
    const float h0d = __ldg(&h0_[d]);

    #pragma unroll 1
    for (int i = 0; i < CHUNK; i += 4) {
        float buf[4];
        #pragma unroll
        for (int j = 0; j < 4; j++) {
            // partial h(t) over this thread's 4 packed pairs (8 poles)
            const u64 s = add2(add2(XM[0], XM[1]), add2(XM[2], XM[3]));
            float slo, shi; unpk2(s, slo, shi);
            float part = slo + shi;
            // merge the 4 pole-quarters (lanes q*8+c3, same c3)
            part += __shfl_xor_sync(0xFFFFFFFFu, part, 8);
            part += __shfl_xor_sync(0xFFFFFFFFu, part, 16);
            buf[j] = part;

            // advance the 8 recurrences (4 packed pairs)
            #pragma unroll
            for (int kp = 0; kp < KP; kp++) {
                const u64 xn = fma2(A[kp], X[kp], mul2(B[kp], XM[kp]));
                XM[kp] = X[kp];
                X[kp]  = xn;
            }
        }
        if (i == 0 && c == 0) buf[0] = h0d;   // output position j=0 is h_0[d]
        if (q == 0) {                         // one lane per chunk stores
            float4 v; v.x = buf[0]; v.y = buf[1]; v.z = buf[2]; v.w = buf[3];
            *reinterpret_cast<float4*>(op + i) = v;   // 16B aligned: 64c + 4i
        }
    }
}

} // namespace

extern "C" void kernel_launch(void* const* d_in, const int* in_sizes, int n_in,
                              void* d_out, int out_size) {
    const float* rr  = (const float*)d_in[0];   // r      (K, D)
    const float* th  = (const float*)d_in[1];   // theta  (K, D)
    const float* Rre = (const float*)d_in[2];   // R_re   (K, D)
    const float* Rim = (const float*)d_in[3];   // R_im   (K, D)
    const float* h0  = (const float*)d_in[4];   // h_0    (1, D)
    (void)in_sizes; (void)n_in; (void)out_size; // shapes fixed: K=32, D=1024, L=2048

    // 1024 rows x 32 chunks x 4 pole-quarters = 131072 threads = 2048 blocks of 64.
    // 14 resident blocks/SM x 148 SMs = 2072 slots >= 2048 -> single wave.
    modal_filter_kernel<<<(DDIM * NCH * 4) / 64, 64>>>(
        rr, th, Rre, Rim, h0, (float*)d_out);
}